// round 3
// baseline (speedup 1.0000x reference)
#include <cuda_runtime.h>

static constexpr int NN = 50000;
static constexpr int EE = 600000;
static constexpr int GG = 64;
static constexpr int HH = 128;
static constexpr int BM = 64;     // rows per block
static constexpr int BK = 16;
static constexpr int TPB = 128;

// ---------------- scratch (no allocations allowed) ----------------
__device__ int   d_row[EE];
__device__ int   d_col[EE];
__device__ int   d_batch[NN];
__device__ int   d_is64;
__device__ float d_e_sum[NN * HH];    // per-node edge sums (scatter target)
__device__ float d_e_aggr[NN * HH];   // per-node edge means
__device__ float d_cnt[NN];           // per-node edge counts
__device__ float d_e_mean[GG * HH];
__device__ float d_v_mean[GG * HH];
__device__ int   d_start[GG + 1];

__device__ __forceinline__ float softplusf(float v) {
    // max(v,0) + log1p(exp(-|v|)) with fast MUFU exp/log
    float t = __expf(-fabsf(v));
    return fmaxf(v, 0.0f) + __logf(1.0f + t);
}

// Detect whether index tensors are int64 (odd 32-bit words all zero since
// values < 50000) or int32 (odd words are random indices).
__global__ void detect_kernel(const int* __restrict__ ei) {
    if (blockIdx.x == 0 && threadIdx.x == 0) {
        int all0 = 1;
        for (int i = 0; i < 64; ++i)
            if (ei[2 * i + 1] != 0) { all0 = 0; break; }
        d_is64 = all0;
    }
}

__global__ void convert_kernel(const int* __restrict__ ei, const int* __restrict__ batch) {
    int i = blockIdx.x * 256 + threadIdx.x;
    int is64 = d_is64;
    if (i < EE) {
        d_row[i] = is64 ? ei[2 * i]            : ei[i];
        d_col[i] = is64 ? ei[2 * EE + 2 * i]   : ei[EE + i];
    }
    if (i < NN) {
        d_batch[i] = is64 ? batch[2 * i] : batch[i];
    }
}

__global__ void zero_kernel() {
    int i = blockIdx.x * 256 + threadIdx.x;
    if (i < NN * HH) d_e_sum[i] = 0.0f;
    if (i < NN) d_cnt[i] = 0.0f;
}

__global__ void seg_starts_kernel() {
    int v = blockIdx.x * 256 + threadIdx.x;
    if (v >= NN) return;
    int b = d_batch[v];
    int bp = (v == 0) ? -1 : d_batch[v - 1];
    for (int g = bp + 1; g <= b; ++g) d_start[g] = v;
    if (v == NN - 1)
        for (int g = b + 1; g <= GG; ++g) d_start[g] = NN;
}

__global__ void eaggr_kernel() {
    int i = blockIdx.x * 256 + threadIdx.x;
    if (i < NN * HH) {
        float c = d_cnt[i >> 7];
        d_e_aggr[i] = d_e_sum[i] / fmaxf(c, 1.0f);
    }
}

// Fused: out = softplus(softplus(gather(in) @ W1 + b1) @ W2 + b2)
// EDGE: in = [x[row], x[col], edge_attr, u[batch[row]]]  (K=512), + scatter
// NODE: in = [x, e_aggr, u[batch]]                       (K=384)
template<int NSEG, bool EDGE>
__global__ void __launch_bounds__(TPB)
mlp2_kernel(const float* __restrict__ s0, const float* __restrict__ s1,
            const float* __restrict__ s2, const float* __restrict__ s3,
            const float* __restrict__ W1, const float* __restrict__ b1,
            const float* __restrict__ W2, const float* __restrict__ b2,
            float* __restrict__ outp, int M)
{
    __shared__ float As[BK][72];      // stride 72: 16B-aligned rows
    __shared__ float Bs[BK][128];
    __shared__ float Hs[BM][132];     // layer-1 activations
    __shared__ int   base[BM][4];

    const int tid = threadIdx.x;
    const int tx = tid & 15;
    const int ty = tid >> 4;
    const int m0 = blockIdx.x * BM;

    if (tid < BM) {
        int r = m0 + tid;
        int b0 = 0, b1_ = 0, b2_ = 0, b3_ = 0;
        if (r < M) {
            if (EDGE) {
                int row = d_row[r];
                b0 = row * HH;
                b1_ = d_col[r] * HH;
                b2_ = r * HH;
                b3_ = d_batch[row] * HH;
            } else {
                b0 = r * HH;
                b1_ = r * HH;
                b2_ = d_batch[r] * HH;
            }
        }
        base[tid][0] = b0; base[tid][1] = b1_;
        base[tid][2] = b2_; base[tid][3] = b3_;
    }
    __syncthreads();

    float acc[8][8];
    #pragma unroll
    for (int i = 0; i < 8; ++i)
        #pragma unroll
        for (int j = 0; j < 8; ++j) acc[i][j] = 0.0f;

    // ---------------- layer 1: [BM x K1] @ [K1 x 128] ----------------
    const int K1 = NSEG * HH;
    for (int kt = 0; kt < K1 / BK; ++kt) {
        int k0 = kt * BK;
        int seg = k0 >> 7;          // constant per kt (128 % 16 == 0)
        int c0 = k0 & 127;
        const float* sp;
        if (seg == 0)      sp = s0;
        else if (seg == 1) sp = EDGE ? s1 : d_e_aggr;
        else if (seg == 2) sp = s2;
        else               sp = s3;

        #pragma unroll
        for (int j = 0; j < 2; ++j) {              // 2*128 thr * 4 = 1024 = 16*64
            int q = tid + j * TPB;
            int m = q >> 2, f = q & 3;
            float4 v = *(const float4*)(sp + base[m][seg] + c0 + f * 4);
            As[f * 4 + 0][m] = v.x;
            As[f * 4 + 1][m] = v.y;
            As[f * 4 + 2][m] = v.z;
            As[f * 4 + 3][m] = v.w;
        }
        #pragma unroll
        for (int j = 0; j < 4; ++j) {              // 4*128 thr * 4 = 2048 = 16*128
            int q = tid + j * TPB;
            int k = q >> 5, c = (q & 31) * 4;
            *(float4*)&Bs[k][c] = *(const float4*)(W1 + (k0 + k) * HH + c);
        }
        __syncthreads();
        #pragma unroll
        for (int kk = 0; kk < BK; ++kk) {
            float a[8], b[8];
            *(float4*)(a)     = *(const float4*)&As[kk][ty * 4];
            *(float4*)(a + 4) = *(const float4*)&As[kk][32 + ty * 4];
            *(float4*)(b)     = *(const float4*)&Bs[kk][tx * 4];
            *(float4*)(b + 4) = *(const float4*)&Bs[kk][64 + tx * 4];
            #pragma unroll
            for (int i = 0; i < 8; ++i)
                #pragma unroll
                for (int j = 0; j < 8; ++j)
                    acc[i][j] += a[i] * b[j];
        }
        __syncthreads();
    }

    // bias + softplus, stage h1 into SMEM
    #pragma unroll
    for (int i = 0; i < 8; ++i) {
        int mi = (i < 4) ? ty * 4 + i : 32 + ty * 4 + (i - 4);
        #pragma unroll
        for (int j = 0; j < 8; ++j) {
            int nj = (j < 4) ? tx * 4 + j : 64 + tx * 4 + (j - 4);
            acc[i][j] = softplusf(acc[i][j] + b1[nj]);
        }
        *(float4*)&Hs[mi][tx * 4]      = make_float4(acc[i][0], acc[i][1], acc[i][2], acc[i][3]);
        *(float4*)&Hs[mi][64 + tx * 4] = make_float4(acc[i][4], acc[i][5], acc[i][6], acc[i][7]);
    }
    __syncthreads();

    #pragma unroll
    for (int i = 0; i < 8; ++i)
        #pragma unroll
        for (int j = 0; j < 8; ++j) acc[i][j] = 0.0f;

    // ---------------- layer 2: [BM x 128] @ [128 x 128] ----------------
    for (int kt = 0; kt < HH / BK; ++kt) {
        #pragma unroll
        for (int j = 0; j < 4; ++j) {
            int q = tid + j * TPB;
            int k = q >> 5, c = (q & 31) * 4;
            *(float4*)&Bs[k][c] = *(const float4*)(W2 + (kt * BK + k) * HH + c);
        }
        __syncthreads();
        #pragma unroll
        for (int kk = 0; kk < BK; ++kk) {
            int kg = kt * BK + kk;
            float a[8], b[8];
            #pragma unroll
            for (int i = 0; i < 8; ++i) {
                int mi = (i < 4) ? ty * 4 + i : 32 + ty * 4 + (i - 4);
                a[i] = Hs[mi][kg];
            }
            *(float4*)(b)     = *(const float4*)&Bs[kk][tx * 4];
            *(float4*)(b + 4) = *(const float4*)&Bs[kk][64 + tx * 4];
            #pragma unroll
            for (int i = 0; i < 8; ++i)
                #pragma unroll
                for (int j = 0; j < 8; ++j)
                    acc[i][j] += a[i] * b[j];
        }
        __syncthreads();
    }

    // ---------------- epilogue: bias + softplus + store (+ scatter) ----------------
    #pragma unroll
    for (int i = 0; i < 8; ++i) {
        int mi = (i < 4) ? ty * 4 + i : 32 + ty * 4 + (i - 4);
        int r = m0 + mi;
        if (r < M) {
            float v[8];
            #pragma unroll
            for (int j = 0; j < 8; ++j) {
                int nj = (j < 4) ? tx * 4 + j : 64 + tx * 4 + (j - 4);
                v[j] = softplusf(acc[i][j] + b2[nj]);
            }
            *(float4*)(outp + (size_t)r * HH + tx * 4)      = make_float4(v[0], v[1], v[2], v[3]);
            *(float4*)(outp + (size_t)r * HH + 64 + tx * 4) = make_float4(v[4], v[5], v[6], v[7]);
            if (EDGE) {
                int db = base[mi][0];  // row * H
                #pragma unroll
                for (int j = 0; j < 8; ++j) {
                    int nj = (j < 4) ? tx * 4 + j : 64 + tx * 4 + (j - 4);
                    atomicAdd(&d_e_sum[db + nj], v[j]);
                }
                if (tx == 0) atomicAdd(&d_cnt[db >> 7], 1.0f);
            }
        }
    }
}

// per-graph means of edge sums and node outputs (batch is sorted)
__global__ void graph_reduce_kernel(const float* __restrict__ xnew) {
    int g = blockIdx.x;
    int n = threadIdx.x;
    int s = d_start[g], e = d_start[g + 1];
    float se = 0.0f, sv = 0.0f;
    for (int v = s; v < e; ++v) {
        se += d_e_sum[v * HH + n];
        sv += xnew[(size_t)v * HH + n];
    }
    float sc = 0.0f;
    for (int v = s + n; v < e; v += HH) sc += d_cnt[v];
    __shared__ float red[HH];
    red[n] = sc;
    __syncthreads();
    for (int off = 64; off > 0; off >>= 1) {
        if (n < off) red[n] += red[n + off];
        __syncthreads();
    }
    float ec = red[0];
    d_e_mean[g * HH + n] = se / fmaxf(ec, 1.0f);
    d_v_mean[g * HH + n] = sv / fmaxf((float)(e - s), 1.0f);
}

__global__ void global_mlp_kernel(const float* __restrict__ u,
                                  const float* __restrict__ W1, const float* __restrict__ b1,
                                  const float* __restrict__ W2, const float* __restrict__ b2,
                                  float* __restrict__ out_u) {
    __shared__ float in[3 * HH];
    __shared__ float h1s[HH];
    int g = blockIdx.x, n = threadIdx.x;
    in[n]          = u[g * HH + n];
    in[HH + n]     = d_e_mean[g * HH + n];
    in[2 * HH + n] = d_v_mean[g * HH + n];
    __syncthreads();
    float a = b1[n];
    for (int k = 0; k < 3 * HH; ++k) a += in[k] * W1[k * HH + n];
    h1s[n] = softplusf(a);
    __syncthreads();
    float o = b2[n];
    for (int k = 0; k < HH; ++k) o += h1s[k] * W2[k * HH + n];
    out_u[g * HH + n] = softplusf(o);
}

extern "C" void kernel_launch(void* const* d_in, const int* in_sizes, int n_in,
                              void* d_out, int out_size) {
    const float* x     = (const float*)d_in[0];
    const int*   ei    = (const int*)d_in[1];     // int32 or int64 (detected on device)
    const float* ea    = (const float*)d_in[2];
    const float* u     = (const float*)d_in[3];
    const int*   batch = (const int*)d_in[4];
    const float* We1 = (const float*)d_in[5];
    const float* be1 = (const float*)d_in[6];
    const float* We2 = (const float*)d_in[7];
    const float* be2 = (const float*)d_in[8];
    const float* Wv1 = (const float*)d_in[9];
    const float* bv1 = (const float*)d_in[10];
    const float* Wv2 = (const float*)d_in[11];
    const float* bv2 = (const float*)d_in[12];
    const float* Wu1 = (const float*)d_in[13];
    const float* bu1 = (const float*)d_in[14];
    const float* Wu2 = (const float*)d_in[15];
    const float* bu2 = (const float*)d_in[16];

    float* out   = (float*)d_out;
    float* out_x = out;                            // [N,H]
    float* out_e = out + (size_t)NN * HH;          // [E,H]
    float* out_u = out + (size_t)(NN + EE) * HH;   // [G,H]

    detect_kernel<<<1, 32>>>(ei);
    convert_kernel<<<(EE + 255) / 256, 256>>>(ei, batch);
    zero_kernel<<<(NN * HH + 255) / 256, 256>>>();
    seg_starts_kernel<<<(NN + 255) / 256, 256>>>();

    // edge MLP + scatter
    mlp2_kernel<4, true><<<(EE + BM - 1) / BM, TPB>>>(
        x, x, ea, u, We1, be1, We2, be2, out_e, EE);

    // e_aggr = e_sum / max(cnt,1)
    eaggr_kernel<<<(NN * HH + 255) / 256, 256>>>();

    // node MLP (s1 slot resolved to d_e_aggr inside the kernel)
    mlp2_kernel<3, false><<<(NN + BM - 1) / BM, TPB>>>(
        x, nullptr, u, u, Wv1, bv1, Wv2, bv2, out_x, NN);

    // per-graph means + global MLP
    graph_reduce_kernel<<<GG, HH>>>(out_x);
    global_mlp_kernel<<<GG, HH>>>(u, Wu1, bu1, Wu2, bu2, out_u);
}

// round 6
// speedup vs baseline: 1.5450x; 1.5450x over previous
#include <cuda_runtime.h>
#include <cuda_bf16.h>
#include <cstdint>

static constexpr int NN = 50000;
static constexpr int EE = 600000;
static constexpr int GG = 64;
static constexpr int HH = 128;
static constexpr int TPB = 256;   // 8 warps

// ---------------- scratch (no allocations allowed) ----------------
__device__ int   d_row[EE];
__device__ int   d_col[EE];
__device__ int   d_batch[NN];
__device__ int   d_is64;
__device__ float d_e_sum[NN * HH];
__device__ float d_e_aggr[NN * HH];
__device__ float d_cnt[NN];
__device__ float d_e_mean[GG * HH];
__device__ float d_v_mean[GG * HH];
__device__ int   d_start[GG + 1];
__device__ __nv_bfloat16 d_W1h[HH * 4 * HH];  // [N=128][K] transposed, hi
__device__ __nv_bfloat16 d_W1l[HH * 4 * HH];
__device__ __nv_bfloat16 d_W2h[HH * HH];
__device__ __nv_bfloat16 d_W2l[HH * HH];
__device__ __nv_bfloat16 d_V1h[HH * 3 * HH];
__device__ __nv_bfloat16 d_V1l[HH * 3 * HH];
__device__ __nv_bfloat16 d_V2h[HH * HH];
__device__ __nv_bfloat16 d_V2l[HH * HH];

// ---------------- helpers ----------------
__device__ __forceinline__ uint32_t smem_u32(const void* p) {
    uint32_t a;
    asm("{ .reg .u64 t; cvta.to.shared.u64 t, %1; cvt.u32.u64 %0, t; }" : "=r"(a) : "l"(p));
    return a;
}
__device__ __forceinline__ void ldsm4(uint32_t* r, uint32_t addr) {
    asm volatile("ldmatrix.sync.aligned.m8n8.x4.shared.b16 {%0,%1,%2,%3}, [%4];"
        : "=r"(r[0]), "=r"(r[1]), "=r"(r[2]), "=r"(r[3]) : "r"(addr));
}
__device__ __forceinline__ void ldsm2(uint32_t* r, uint32_t addr) {
    asm volatile("ldmatrix.sync.aligned.m8n8.x2.shared.b16 {%0,%1}, [%2];"
        : "=r"(r[0]), "=r"(r[1]) : "r"(addr));
}
__device__ __forceinline__ void mma_bf16(float* c, const uint32_t* a, const uint32_t* b) {
    asm volatile("mma.sync.aligned.m16n8k16.row.col.f32.bf16.bf16.f32 "
        "{%0,%1,%2,%3}, {%4,%5,%6,%7}, {%8,%9}, {%0,%1,%2,%3};"
        : "+f"(c[0]), "+f"(c[1]), "+f"(c[2]), "+f"(c[3])
        : "r"(a[0]), "r"(a[1]), "r"(a[2]), "r"(a[3]), "r"(b[0]), "r"(b[1]));
}
// pack two floats as bf16x2: low half = lo, high half = hi
__device__ __forceinline__ uint32_t cvt2bf(float lo, float hi) {
    uint32_t r;
    asm("cvt.rn.bf16x2.f32 %0, %1, %2;" : "=r"(r) : "f"(hi), "f"(lo));
    return r;
}
// split pair into (hi bf16x2, lo bf16x2)
__device__ __forceinline__ void split2(float a, float b, uint32_t& h, uint32_t& l) {
    h = cvt2bf(a, b);
    float fa = __uint_as_float(h << 16);
    float fb = __uint_as_float(h & 0xFFFF0000u);
    l = cvt2bf(a - fa, b - fb);
}
__device__ __forceinline__ float softplusf(float v) {
    float t = __expf(-fabsf(v));
    return fmaxf(v, 0.0f) + __logf(1.0f + t);
}

// ---------------- small prep kernels ----------------
__global__ void detect_kernel(const int* __restrict__ ei) {
    if (threadIdx.x == 0) {
        int all0 = 1;
        for (int i = 0; i < 64; ++i)
            if (ei[2 * i + 1] != 0) { all0 = 0; break; }
        d_is64 = all0;
    }
}
__global__ void convert_kernel(const int* __restrict__ ei, const int* __restrict__ batch) {
    int i = blockIdx.x * 256 + threadIdx.x;
    int is64 = d_is64;
    if (i < EE) {
        d_row[i] = is64 ? ei[2 * i]          : ei[i];
        d_col[i] = is64 ? ei[2 * EE + 2 * i] : ei[EE + i];
    }
    if (i < NN) d_batch[i] = is64 ? batch[2 * i] : batch[i];
}
__global__ void zero_kernel() {
    int i = blockIdx.x * 256 + threadIdx.x;
    if (i < NN * HH) d_e_sum[i] = 0.0f;
    if (i < NN) d_cnt[i] = 0.0f;
}
__global__ void seg_starts_kernel() {
    int v = blockIdx.x * 256 + threadIdx.x;
    if (v >= NN) return;
    int b = d_batch[v];
    int bp = (v == 0) ? -1 : d_batch[v - 1];
    for (int g = bp + 1; g <= b; ++g) d_start[g] = v;
    if (v == NN - 1)
        for (int g = b + 1; g <= GG; ++g) d_start[g] = NN;
}
__global__ void eaggr_kernel() {
    int i = blockIdx.x * 256 + threadIdx.x;
    if (i < NN * HH) {
        float c = d_cnt[i >> 7];
        d_e_aggr[i] = d_e_sum[i] / fmaxf(c, 1.0f);
    }
}
// W [K][N] row-major -> Wh/Wl [N][K] bf16 hi/lo (transpose + split)
__global__ void prep_w(const float* __restrict__ W, __nv_bfloat16* __restrict__ Wh,
                       __nv_bfloat16* __restrict__ Wl, int K, int N) {
    int i = blockIdx.x * 256 + threadIdx.x;
    if (i < K * N) {
        int k = i / N, n = i % N;
        float v = W[i];
        __nv_bfloat16 h = __float2bfloat16(v);
        float r = v - __bfloat162float(h);
        Wh[n * K + k] = h;
        Wl[n * K + k] = __float2bfloat16(r);
    }
}

// ---------------- fused 2-layer MLP via mma.sync bf16 hi/lo split ----------------
// EDGE: in = [x[row], x[col], edge_attr, u[batch[row]]] (K=512), + scatter
// NODE: in = [x, e_aggr, u[batch]]                      (K=384)
// Dynamic smem layout (94208 B):
//   [0]      base[128][4]            (2048)
//   [2048]   sAh [128][48B]          (6144)
//   [8192]   sAl                     (6144)
//   [14336]  sBh                     (6144)
//   [20480]  sBl                     (6144)
//   [26624]  sH1h [128][272B]        (34816)
//   [61440]  sH1l                    (34816)  -> total 96256
template<int NSEG, bool EDGE>
__global__ void __launch_bounds__(TPB, 2)
mlp2_mma(const float* __restrict__ s0, const float* __restrict__ s1,
         const float* __restrict__ s2, const float* __restrict__ s3,
         const __nv_bfloat16* __restrict__ W1h, const __nv_bfloat16* __restrict__ W1l,
         const float* __restrict__ b1,
         const __nv_bfloat16* __restrict__ W2h, const __nv_bfloat16* __restrict__ W2l,
         const float* __restrict__ b2,
         float* __restrict__ outp, int M)
{
    extern __shared__ char sm[];
    int* base = (int*)sm;
    char* sAh = sm + 2048;
    char* sAl = sm + 8192;
    char* sBh = sm + 14336;
    char* sBl = sm + 20480;
    char* sH1h = sm + 26624;
    char* sH1l = sm + 61440;
    const uint32_t aAh = smem_u32(sAh), aAl = smem_u32(sAl);
    const uint32_t aBh = smem_u32(sBh), aBl = smem_u32(sBl);
    const uint32_t aH1h = smem_u32(sH1h), aH1l = smem_u32(sH1l);

    const int tid = threadIdx.x;
    const int w = tid >> 5, l = tid & 31;
    const int m0 = blockIdx.x * 128;

    if (tid < 128) {
        int r = m0 + tid;
        int b0 = 0, b1_ = 0, b2_ = 0, b3_ = 0;
        if (r < M) {
            if (EDGE) {
                int row = d_row[r];
                b0 = row * HH;
                b1_ = d_col[r] * HH;
                b2_ = r * HH;
                b3_ = d_batch[row] * HH;
            } else {
                b0 = r * HH;
                b1_ = r * HH;
                b2_ = d_batch[r] * HH;
            }
        }
        base[tid * 4 + 0] = b0; base[tid * 4 + 1] = b1_;
        base[tid * 4 + 2] = b2_; base[tid * 4 + 3] = b3_;
    }
    __syncthreads();

    const int row = tid >> 1, half = tid & 1;   // staging assignment
    const int K1 = NSEG * 128;

    // ldmatrix lane offsets
    const uint32_t aoff = (uint32_t)((16 * w + (l & 15)) * 48 + (l >> 4) * 16);
    const int lb = l & 15;
    const uint32_t boff = (uint32_t)((lb & 7) * 48 + (lb >> 3) * 16);
    const uint32_t hoff = (uint32_t)((16 * w + (l & 15)) * 272 + (l >> 4) * 16);

    float acc[16][4];
    #pragma unroll
    for (int j = 0; j < 16; ++j)
        #pragma unroll
        for (int q = 0; q < 4; ++q) acc[j][q] = 0.0f;

    // ---------------- layer 1 ----------------
    for (int c = 0; c < NSEG * 8; ++c) {
        const int k0 = c * 16;
        const int seg = k0 >> 7;
        const float* sp = (seg == 0) ? s0
                        : (seg == 1) ? (EDGE ? s1 : d_e_aggr)
                        : (seg == 2) ? s2 : s3;
        const float* ap = sp + base[row * 4 + seg] + (k0 & 127) + half * 8;
        float4 f0 = *(const float4*)ap;
        float4 f1 = *(const float4*)(ap + 4);
        uint4 wbh = *(const uint4*)(W1h + row * K1 + k0 + half * 8);
        uint4 wbl = *(const uint4*)(W1l + row * K1 + k0 + half * 8);

        __syncthreads();   // previous chunk's ldmatrix complete
        uint4 Ahv, Alv;
        split2(f0.x, f0.y, Ahv.x, Alv.x);
        split2(f0.z, f0.w, Ahv.y, Alv.y);
        split2(f1.x, f1.y, Ahv.z, Alv.z);
        split2(f1.z, f1.w, Ahv.w, Alv.w);
        *(uint4*)(sAh + row * 48 + half * 16) = Ahv;
        *(uint4*)(sAl + row * 48 + half * 16) = Alv;
        *(uint4*)(sBh + row * 48 + half * 16) = wbh;
        *(uint4*)(sBl + row * 48 + half * 16) = wbl;
        __syncthreads();

        uint32_t ah[4], al[4];
        ldsm4(ah, aAh + aoff);
        ldsm4(al, aAl + aoff);
        #pragma unroll
        for (int j = 0; j < 16; ++j) {
            uint32_t bh[2], bl[2];
            ldsm2(bh, aBh + boff + j * 384);
            ldsm2(bl, aBl + boff + j * 384);
            mma_bf16(acc[j], ah, bh);
            mma_bf16(acc[j], ah, bl);
            mma_bf16(acc[j], al, bh);
        }
    }

    // ---------------- layer-1 epilogue: bias + softplus -> sH1 (bf16 hi/lo) ----------------
    {
        const int r0 = 16 * w + (l >> 2);
        #pragma unroll
        for (int j = 0; j < 16; ++j) {
            int col = j * 8 + 2 * (l & 3);
            float bb0 = __ldg(b1 + col), bb1 = __ldg(b1 + col + 1);
            float h00 = softplusf(acc[j][0] + bb0);
            float h01 = softplusf(acc[j][1] + bb1);
            float h10 = softplusf(acc[j][2] + bb0);
            float h11 = softplusf(acc[j][3] + bb1);
            uint32_t hh, hl;
            split2(h00, h01, hh, hl);
            *(uint32_t*)(sH1h + r0 * 272 + col * 2) = hh;
            *(uint32_t*)(sH1l + r0 * 272 + col * 2) = hl;
            split2(h10, h11, hh, hl);
            *(uint32_t*)(sH1h + (r0 + 8) * 272 + col * 2) = hh;
            *(uint32_t*)(sH1l + (r0 + 8) * 272 + col * 2) = hl;
            acc[j][0] = acc[j][1] = acc[j][2] = acc[j][3] = 0.0f;
        }
    }

    // ---------------- layer 2 ----------------
    for (int c = 0; c < 8; ++c) {
        const int k0 = c * 16;
        uint4 wbh = *(const uint4*)(W2h + row * 128 + k0 + half * 8);
        uint4 wbl = *(const uint4*)(W2l + row * 128 + k0 + half * 8);
        __syncthreads();   // also orders sH1 writes before ldsm reads (first iter)
        *(uint4*)(sBh + row * 48 + half * 16) = wbh;
        *(uint4*)(sBl + row * 48 + half * 16) = wbl;
        __syncthreads();

        uint32_t ah[4], al[4];
        ldsm4(ah, aH1h + hoff + k0 * 2);
        ldsm4(al, aH1l + hoff + k0 * 2);
        #pragma unroll
        for (int j = 0; j < 16; ++j) {
            uint32_t bh[2], bl[2];
            ldsm2(bh, aBh + boff + j * 384);
            ldsm2(bl, aBl + boff + j * 384);
            mma_bf16(acc[j], ah, bh);
            mma_bf16(acc[j], ah, bl);
            mma_bf16(acc[j], al, bh);
        }
    }

    // ---------------- epilogue 2: bias + softplus + store (+ scatter) ----------------
    {
        const int r0l = 16 * w + (l >> 2);          // local rows r0l, r0l+8
        const int r0 = m0 + r0l;
        const int db0 = EDGE ? base[r0l * 4 + 0] : 0;
        const int db1 = EDGE ? base[(r0l + 8) * 4 + 0] : 0;
        #pragma unroll
        for (int j = 0; j < 16; ++j) {
            int col = j * 8 + 2 * (l & 3);
            float bb0 = __ldg(b2 + col), bb1 = __ldg(b2 + col + 1);
            float o00 = softplusf(acc[j][0] + bb0);
            float o01 = softplusf(acc[j][1] + bb1);
            float o10 = softplusf(acc[j][2] + bb0);
            float o11 = softplusf(acc[j][3] + bb1);
            if (r0 < M) {
                *(float2*)(outp + (size_t)r0 * HH + col) = make_float2(o00, o01);
                if (EDGE) {
                    atomicAdd(&d_e_sum[db0 + col], o00);
                    atomicAdd(&d_e_sum[db0 + col + 1], o01);
                }
            }
            if (r0 + 8 < M) {
                *(float2*)(outp + (size_t)(r0 + 8) * HH + col) = make_float2(o10, o11);
                if (EDGE) {
                    atomicAdd(&d_e_sum[db1 + col], o10);
                    atomicAdd(&d_e_sum[db1 + col + 1], o11);
                }
            }
        }
        if (EDGE && (l & 3) == 0) {
            if (r0 < M)     atomicAdd(&d_cnt[db0 >> 7], 1.0f);
            if (r0 + 8 < M) atomicAdd(&d_cnt[db1 >> 7], 1.0f);
        }
    }
}

// ---------------- per-graph reductions + global MLP ----------------
__global__ void graph_reduce_kernel(const float* __restrict__ xnew) {
    int g = blockIdx.x;
    int n = threadIdx.x;
    int s = d_start[g], e = d_start[g + 1];
    float se = 0.0f, sv = 0.0f;
    for (int v = s; v < e; ++v) {
        se += d_e_sum[v * HH + n];
        sv += xnew[(size_t)v * HH + n];
    }
    float sc = 0.0f;
    for (int v = s + n; v < e; v += HH) sc += d_cnt[v];
    __shared__ float red[HH];
    red[n] = sc;
    __syncthreads();
    for (int off = 64; off > 0; off >>= 1) {
        if (n < off) red[n] += red[n + off];
        __syncthreads();
    }
    float ec = red[0];
    d_e_mean[g * HH + n] = se / fmaxf(ec, 1.0f);
    d_v_mean[g * HH + n] = sv / fmaxf((float)(e - s), 1.0f);
}

__global__ void global_mlp_kernel(const float* __restrict__ u,
                                  const float* __restrict__ W1, const float* __restrict__ b1,
                                  const float* __restrict__ W2, const float* __restrict__ b2,
                                  float* __restrict__ out_u) {
    __shared__ float in[3 * HH];
    __shared__ float h1s[HH];
    int g = blockIdx.x, n = threadIdx.x;
    in[n]          = u[g * HH + n];
    in[HH + n]     = d_e_mean[g * HH + n];
    in[2 * HH + n] = d_v_mean[g * HH + n];
    __syncthreads();
    float a = b1[n];
    for (int k = 0; k < 3 * HH; ++k) a += in[k] * W1[k * HH + n];
    h1s[n] = softplusf(a);
    __syncthreads();
    float o = b2[n];
    for (int k = 0; k < HH; ++k) o += h1s[k] * W2[k * HH + n];
    out_u[g * HH + n] = softplusf(o);
}

// ---------------- launch ----------------
extern "C" void kernel_launch(void* const* d_in, const int* in_sizes, int n_in,
                              void* d_out, int out_size) {
    const float* x     = (const float*)d_in[0];
    const int*   ei    = (const int*)d_in[1];
    const float* ea    = (const float*)d_in[2];
    const float* u     = (const float*)d_in[3];
    const int*   batch = (const int*)d_in[4];
    const float* We1 = (const float*)d_in[5];
    const float* be1 = (const float*)d_in[6];
    const float* We2 = (const float*)d_in[7];
    const float* be2 = (const float*)d_in[8];
    const float* Wv1 = (const float*)d_in[9];
    const float* bv1 = (const float*)d_in[10];
    const float* Wv2 = (const float*)d_in[11];
    const float* bv2 = (const float*)d_in[12];
    const float* Wu1 = (const float*)d_in[13];
    const float* bu1 = (const float*)d_in[14];
    const float* Wu2 = (const float*)d_in[15];
    const float* bu2 = (const float*)d_in[16];

    float* out   = (float*)d_out;
    float* out_x = out;
    float* out_e = out + (size_t)NN * HH;
    float* out_u = out + (size_t)(NN + EE) * HH;

    __nv_bfloat16 *pW1h, *pW1l, *pW2h, *pW2l, *pV1h, *pV1l, *pV2h, *pV2l;
    cudaGetSymbolAddress((void**)&pW1h, d_W1h);
    cudaGetSymbolAddress((void**)&pW1l, d_W1l);
    cudaGetSymbolAddress((void**)&pW2h, d_W2h);
    cudaGetSymbolAddress((void**)&pW2l, d_W2l);
    cudaGetSymbolAddress((void**)&pV1h, d_V1h);
    cudaGetSymbolAddress((void**)&pV1l, d_V1l);
    cudaGetSymbolAddress((void**)&pV2h, d_V2h);
    cudaGetSymbolAddress((void**)&pV2l, d_V2l);

    const int SMEM = 96256;
    cudaFuncSetAttribute(mlp2_mma<4, true>,  cudaFuncAttributeMaxDynamicSharedMemorySize, SMEM);
    cudaFuncSetAttribute(mlp2_mma<3, false>, cudaFuncAttributeMaxDynamicSharedMemorySize, SMEM);

    detect_kernel<<<1, 32>>>(ei);
    convert_kernel<<<(EE + 255) / 256, 256>>>(ei, batch);
    zero_kernel<<<(NN * HH + 255) / 256, 256>>>();
    seg_starts_kernel<<<(NN + 255) / 256, 256>>>();

    prep_w<<<(4 * HH * HH + 255) / 256, 256>>>(We1, pW1h, pW1l, 4 * HH, HH);
    prep_w<<<(HH * HH + 255) / 256, 256>>>(We2, pW2h, pW2l, HH, HH);
    prep_w<<<(3 * HH * HH + 255) / 256, 256>>>(Wv1, pV1h, pV1l, 3 * HH, HH);
    prep_w<<<(HH * HH + 255) / 256, 256>>>(Wv2, pV2h, pV2l, HH, HH);

    // edge MLP + scatter
    mlp2_mma<4, true><<<(EE + 127) / 128, TPB, SMEM>>>(
        x, x, ea, u, pW1h, pW1l, be1, pW2h, pW2l, be2, out_e, EE);

    eaggr_kernel<<<(NN * HH + 255) / 256, 256>>>();

    // node MLP
    mlp2_mma<3, false><<<(NN + 127) / 128, TPB, SMEM>>>(
        x, nullptr, u, nullptr, pV1h, pV1l, bv1, pV2h, pV2l, bv2, out_x, NN);

    graph_reduce_kernel<<<GG, HH>>>(out_x);
    global_mlp_kernel<<<GG, HH>>>(u, Wu1, bu1, Wu2, bu2, out_u);
}

// round 7
// speedup vs baseline: 1.8090x; 1.1709x over previous
#include <cuda_runtime.h>
#include <cstdint>

static constexpr int NN = 50000;
static constexpr int EE = 600000;
static constexpr int GG = 64;
static constexpr int HH = 128;
static constexpr int TPB = 256;   // 8 warps

// ---------------- scratch (no allocations allowed) ----------------
__device__ int   d_row[EE];
__device__ int   d_col[EE];
__device__ int   d_batch[NN];
__device__ int   d_is64;
__device__ float d_e_sum[NN * HH];
__device__ float d_e_aggr[NN * HH];
__device__ float d_cnt[NN];
__device__ float d_e_mean[GG * HH];
__device__ float d_v_mean[GG * HH];
__device__ int   d_start[GG + 1];
__device__ float d_W1t[HH * 4 * HH];   // [N=128][K] transposed, tf32-rounded
__device__ float d_W2t[HH * HH];
__device__ float d_V1t[HH * 3 * HH];
__device__ float d_V2t[HH * HH];

// ---------------- helpers ----------------
__device__ __forceinline__ uint32_t smem_u32(const void* p) {
    uint32_t a;
    asm("{ .reg .u64 t; cvta.to.shared.u64 t, %1; cvt.u32.u64 %0, t; }" : "=r"(a) : "l"(p));
    return a;
}
__device__ __forceinline__ void ldsm4(uint32_t* r, uint32_t addr) {
    asm volatile("ldmatrix.sync.aligned.m8n8.x4.shared.b16 {%0,%1,%2,%3}, [%4];"
        : "=r"(r[0]), "=r"(r[1]), "=r"(r[2]), "=r"(r[3]) : "r"(addr));
}
__device__ __forceinline__ void mma_tf32(float* c, const uint32_t* a, uint32_t b0, uint32_t b1) {
    asm volatile("mma.sync.aligned.m16n8k8.row.col.f32.tf32.tf32.f32 "
        "{%0,%1,%2,%3}, {%4,%5,%6,%7}, {%8,%9}, {%0,%1,%2,%3};"
        : "+f"(c[0]), "+f"(c[1]), "+f"(c[2]), "+f"(c[3])
        : "r"(a[0]), "r"(a[1]), "r"(a[2]), "r"(a[3]), "r"(b0), "r"(b1));
}
__device__ __forceinline__ float tf32r(float v) {
    uint32_t r;
    asm("cvt.rna.tf32.f32 %0, %1;" : "=r"(r) : "f"(v));
    return __uint_as_float(r);
}
__device__ __forceinline__ float4 tf32r4(float4 v) {
    return make_float4(tf32r(v.x), tf32r(v.y), tf32r(v.z), tf32r(v.w));
}
__device__ __forceinline__ float softplusf(float v) {
    float t = __expf(-fabsf(v));
    return fmaxf(v, 0.0f) + __logf(1.0f + t);
}

// ---------------- small prep kernels ----------------
__global__ void detect_kernel(const int* __restrict__ ei) {
    if (threadIdx.x == 0) {
        int all0 = 1;
        for (int i = 0; i < 64; ++i)
            if (ei[2 * i + 1] != 0) { all0 = 0; break; }
        d_is64 = all0;
    }
}
__global__ void convert_kernel(const int* __restrict__ ei, const int* __restrict__ batch) {
    int i = blockIdx.x * 256 + threadIdx.x;
    int is64 = d_is64;
    if (i < EE) {
        d_row[i] = is64 ? ei[2 * i]          : ei[i];
        d_col[i] = is64 ? ei[2 * EE + 2 * i] : ei[EE + i];
    }
    if (i < NN) d_batch[i] = is64 ? batch[2 * i] : batch[i];
}
__global__ void zero_kernel() {
    int i = blockIdx.x * 256 + threadIdx.x;
    if (i < NN * HH) d_e_sum[i] = 0.0f;
    if (i < NN) d_cnt[i] = 0.0f;
}
__global__ void seg_starts_kernel() {
    int v = blockIdx.x * 256 + threadIdx.x;
    if (v >= NN) return;
    int b = d_batch[v];
    int bp = (v == 0) ? -1 : d_batch[v - 1];
    for (int g = bp + 1; g <= b; ++g) d_start[g] = v;
    if (v == NN - 1)
        for (int g = b + 1; g <= GG; ++g) d_start[g] = NN;
}
__global__ void eaggr_kernel() {
    int i = blockIdx.x * 256 + threadIdx.x;
    if (i < NN * HH) {
        float c = d_cnt[i >> 7];
        d_e_aggr[i] = d_e_sum[i] / fmaxf(c, 1.0f);
    }
}
// W [K][N] row-major -> Wt [N][K] tf32-rounded fp32
__global__ void prep_w(const float* __restrict__ W, float* __restrict__ Wt, int K, int N) {
    int i = blockIdx.x * 256 + threadIdx.x;
    if (i < K * N) {
        int k = i / N, n = i % N;
        Wt[n * K + k] = tf32r(W[i]);
    }
}

// ---------------- fused 2-layer MLP via mma.sync tf32 single-pass ----------------
// EDGE: in = [x[row], x[col], edge_attr, u[batch[row]]] (K=512), + scatter
// NODE: in = [x, e_aggr, u[batch]]                      (K=384)
// Dynamic smem layout (90112 B):
//   [0]      base[128][4]               (2048)
//   [2048]   sA  [128 rows][20 floats]  (10240)   16 k-cols + 4 pad
//   [12288]  sB  [128 n   ][20 floats]  (10240)
//   [22528]  sH1 [128 rows][132 floats] (67584)
template<int NSEG, bool EDGE>
__global__ void __launch_bounds__(TPB, 2)
mlp2_mma(const float* __restrict__ s0, const float* __restrict__ s1,
         const float* __restrict__ s2, const float* __restrict__ s3,
         const float* __restrict__ W1t, const float* __restrict__ b1,
         const float* __restrict__ W2t, const float* __restrict__ b2,
         float* __restrict__ outp, int M)
{
    extern __shared__ char sm[];
    int* base = (int*)sm;
    char* sA  = sm + 2048;
    char* sB  = sm + 12288;
    char* sH1 = sm + 22528;
    const uint32_t aA = smem_u32(sA), aB = smem_u32(sB), aH1 = smem_u32(sH1);

    const int tid = threadIdx.x;
    const int w = tid >> 5, l = tid & 31;
    const int m0 = blockIdx.x * 128;

    if (tid < 128) {
        int r = m0 + tid;
        int b0 = 0, b1_ = 0, b2_ = 0, b3_ = 0;
        if (r < M) {
            if (EDGE) {
                int row = d_row[r];
                b0 = row * HH;
                b1_ = d_col[r] * HH;
                b2_ = r * HH;
                b3_ = d_batch[row] * HH;
            } else {
                b0 = r * HH;
                b1_ = r * HH;
                b2_ = d_batch[r] * HH;
            }
        }
        base[tid * 4 + 0] = b0; base[tid * 4 + 1] = b1_;
        base[tid * 4 + 2] = b2_; base[tid * 4 + 3] = b3_;
    }
    __syncthreads();

    const int row = tid >> 1, half = tid & 1;   // staging: 8 floats per thread
    const int K1 = NSEG * 128;

    // ldmatrix lane offsets (byte strides: sA/sB rows 80B, sH1 rows 528B)
    const uint32_t aoffA = (uint32_t)((16 * w + (l & 15)) * 80 + (l >> 4) * 16);
    const uint32_t boff4 = (uint32_t)(((l & 7) + ((l >> 4) & 1) * 8) * 80 + ((l >> 3) & 1) * 16);
    const uint32_t hoffA = (uint32_t)((16 * w + (l & 15)) * 528 + (l >> 4) * 16);

    float acc[16][4];
    #pragma unroll
    for (int j = 0; j < 16; ++j)
        #pragma unroll
        for (int q = 0; q < 4; ++q) acc[j][q] = 0.0f;

    // ---------------- layer 1: chunks of k16 ----------------
    for (int c = 0; c < NSEG * 8; ++c) {
        const int k0 = c * 16;
        const int seg = k0 >> 7;
        const float* sp = (seg == 0) ? s0
                        : (seg == 1) ? (EDGE ? s1 : d_e_aggr)
                        : (seg == 2) ? s2 : s3;
        const float* ap = sp + base[row * 4 + seg] + (k0 & 127) + half * 8;
        float4 f0 = *(const float4*)ap;
        float4 f1 = *(const float4*)(ap + 4);
        const float* bp = W1t + row * K1 + k0 + half * 8;
        float4 g0 = *(const float4*)bp;
        float4 g1 = *(const float4*)(bp + 4);

        __syncthreads();   // previous chunk's ldmatrix complete
        *(float4*)(sA + row * 80 + half * 32)      = tf32r4(f0);
        *(float4*)(sA + row * 80 + half * 32 + 16) = tf32r4(f1);
        *(float4*)(sB + row * 80 + half * 32)      = g0;
        *(float4*)(sB + row * 80 + half * 32 + 16) = g1;
        __syncthreads();

        uint32_t a0[4], a1[4];
        ldsm4(a0, aA + aoffA);        // k8 #0 (cols 0-7)
        ldsm4(a1, aA + aoffA + 32);   // k8 #1 (cols 8-15)
        #pragma unroll
        for (int p = 0; p < 8; ++p) {
            uint32_t b[4], b2[4];
            ldsm4(b,  aB + boff4 + p * 1280);        // (b0,b1) for j=2p, (b0,b1) for j=2p+1, k8#0
            ldsm4(b2, aB + boff4 + p * 1280 + 32);   // same, k8#1
            mma_tf32(acc[2 * p],     a0, b[0],  b[1]);
            mma_tf32(acc[2 * p + 1], a0, b[2],  b[3]);
            mma_tf32(acc[2 * p],     a1, b2[0], b2[1]);
            mma_tf32(acc[2 * p + 1], a1, b2[2], b2[3]);
        }
    }

    // ---------------- layer-1 epilogue: bias + softplus -> sH1 (tf32-rounded fp32) ----------------
    {
        const int r0 = 16 * w + (l >> 2);
        #pragma unroll
        for (int j = 0; j < 16; ++j) {
            int col = j * 8 + 2 * (l & 3);
            float bb0 = __ldg(b1 + col), bb1 = __ldg(b1 + col + 1);
            float h00 = tf32r(softplusf(acc[j][0] + bb0));
            float h01 = tf32r(softplusf(acc[j][1] + bb1));
            float h10 = tf32r(softplusf(acc[j][2] + bb0));
            float h11 = tf32r(softplusf(acc[j][3] + bb1));
            *(float2*)(sH1 + r0 * 528 + col * 4)       = make_float2(h00, h01);
            *(float2*)(sH1 + (r0 + 8) * 528 + col * 4) = make_float2(h10, h11);
            acc[j][0] = acc[j][1] = acc[j][2] = acc[j][3] = 0.0f;
        }
    }

    // ---------------- layer 2: K=128, 8 chunks of k16 ----------------
    for (int c = 0; c < 8; ++c) {
        const int k0 = c * 16;
        const float* bp = W2t + row * 128 + k0 + half * 8;
        float4 g0 = *(const float4*)bp;
        float4 g1 = *(const float4*)(bp + 4);
        __syncthreads();   // prev ldsm done; first iter: orders sH1 writes before reads
        *(float4*)(sB + row * 80 + half * 32)      = g0;
        *(float4*)(sB + row * 80 + half * 32 + 16) = g1;
        __syncthreads();

        uint32_t a0[4], a1[4];
        ldsm4(a0, aH1 + hoffA + k0 * 4);
        ldsm4(a1, aH1 + hoffA + k0 * 4 + 32);
        #pragma unroll
        for (int p = 0; p < 8; ++p) {
            uint32_t b[4], b2[4];
            ldsm4(b,  aB + boff4 + p * 1280);
            ldsm4(b2, aB + boff4 + p * 1280 + 32);
            mma_tf32(acc[2 * p],     a0, b[0],  b[1]);
            mma_tf32(acc[2 * p + 1], a0, b[2],  b[3]);
            mma_tf32(acc[2 * p],     a1, b2[0], b2[1]);
            mma_tf32(acc[2 * p + 1], a1, b2[2], b2[3]);
        }
    }

    // ---------------- epilogue 2: bias + softplus + store (+ scatter) ----------------
    {
        const int r0l = 16 * w + (l >> 2);          // local rows r0l, r0l+8
        const int r0 = m0 + r0l;
        const int db0 = EDGE ? base[r0l * 4 + 0] : 0;
        const int db1 = EDGE ? base[(r0l + 8) * 4 + 0] : 0;
        #pragma unroll
        for (int j = 0; j < 16; ++j) {
            int col = j * 8 + 2 * (l & 3);
            float bb0 = __ldg(b2 + col), bb1 = __ldg(b2 + col + 1);
            float o00 = softplusf(acc[j][0] + bb0);
            float o01 = softplusf(acc[j][1] + bb1);
            float o10 = softplusf(acc[j][2] + bb0);
            float o11 = softplusf(acc[j][3] + bb1);
            if (r0 < M) {
                *(float2*)(outp + (size_t)r0 * HH + col) = make_float2(o00, o01);
                if (EDGE) {
                    atomicAdd(&d_e_sum[db0 + col], o00);
                    atomicAdd(&d_e_sum[db0 + col + 1], o01);
                }
            }
            if (r0 + 8 < M) {
                *(float2*)(outp + (size_t)(r0 + 8) * HH + col) = make_float2(o10, o11);
                if (EDGE) {
                    atomicAdd(&d_e_sum[db1 + col], o10);
                    atomicAdd(&d_e_sum[db1 + col + 1], o11);
                }
            }
        }
        if (EDGE && (l & 3) == 0) {
            if (r0 < M)     atomicAdd(&d_cnt[db0 >> 7], 1.0f);
            if (r0 + 8 < M) atomicAdd(&d_cnt[db1 >> 7], 1.0f);
        }
    }
}

// ---------------- per-graph reductions + global MLP ----------------
__global__ void graph_reduce_kernel(const float* __restrict__ xnew) {
    int g = blockIdx.x;
    int n = threadIdx.x;
    int s = d_start[g], e = d_start[g + 1];
    float se = 0.0f, sv = 0.0f;
    for (int v = s; v < e; ++v) {
        se += d_e_sum[v * HH + n];
        sv += xnew[(size_t)v * HH + n];
    }
    float sc = 0.0f;
    for (int v = s + n; v < e; v += HH) sc += d_cnt[v];
    __shared__ float red[HH];
    red[n] = sc;
    __syncthreads();
    for (int off = 64; off > 0; off >>= 1) {
        if (n < off) red[n] += red[n + off];
        __syncthreads();
    }
    float ec = red[0];
    d_e_mean[g * HH + n] = se / fmaxf(ec, 1.0f);
    d_v_mean[g * HH + n] = sv / fmaxf((float)(e - s), 1.0f);
}

__global__ void global_mlp_kernel(const float* __restrict__ u,
                                  const float* __restrict__ W1, const float* __restrict__ b1,
                                  const float* __restrict__ W2, const float* __restrict__ b2,
                                  float* __restrict__ out_u) {
    __shared__ float in[3 * HH];
    __shared__ float h1s[HH];
    int g = blockIdx.x, n = threadIdx.x;
    in[n]          = u[g * HH + n];
    in[HH + n]     = d_e_mean[g * HH + n];
    in[2 * HH + n] = d_v_mean[g * HH + n];
    __syncthreads();
    float a = b1[n];
    for (int k = 0; k < 3 * HH; ++k) a += in[k] * W1[k * HH + n];
    h1s[n] = softplusf(a);
    __syncthreads();
    float o = b2[n];
    for (int k = 0; k < HH; ++k) o += h1s[k] * W2[k * HH + n];
    out_u[g * HH + n] = softplusf(o);
}

// ---------------- launch ----------------
extern "C" void kernel_launch(void* const* d_in, const int* in_sizes, int n_in,
                              void* d_out, int out_size) {
    const float* x     = (const float*)d_in[0];
    const int*   ei    = (const int*)d_in[1];
    const float* ea    = (const float*)d_in[2];
    const float* u     = (const float*)d_in[3];
    const int*   batch = (const int*)d_in[4];
    const float* We1 = (const float*)d_in[5];
    const float* be1 = (const float*)d_in[6];
    const float* We2 = (const float*)d_in[7];
    const float* be2 = (const float*)d_in[8];
    const float* Wv1 = (const float*)d_in[9];
    const float* bv1 = (const float*)d_in[10];
    const float* Wv2 = (const float*)d_in[11];
    const float* bv2 = (const float*)d_in[12];
    const float* Wu1 = (const float*)d_in[13];
    const float* bu1 = (const float*)d_in[14];
    const float* Wu2 = (const float*)d_in[15];
    const float* bu2 = (const float*)d_in[16];

    float* out   = (float*)d_out;
    float* out_x = out;
    float* out_e = out + (size_t)NN * HH;
    float* out_u = out + (size_t)(NN + EE) * HH;

    float *pW1t, *pW2t, *pV1t, *pV2t;
    cudaGetSymbolAddress((void**)&pW1t, d_W1t);
    cudaGetSymbolAddress((void**)&pW2t, d_W2t);
    cudaGetSymbolAddress((void**)&pV1t, d_V1t);
    cudaGetSymbolAddress((void**)&pV2t, d_V2t);

    const int SMEM = 90112;
    cudaFuncSetAttribute(mlp2_mma<4, true>,  cudaFuncAttributeMaxDynamicSharedMemorySize, SMEM);
    cudaFuncSetAttribute(mlp2_mma<3, false>, cudaFuncAttributeMaxDynamicSharedMemorySize, SMEM);

    detect_kernel<<<1, 32>>>(ei);
    convert_kernel<<<(EE + 255) / 256, 256>>>(ei, batch);
    zero_kernel<<<(NN * HH + 255) / 256, 256>>>();
    seg_starts_kernel<<<(NN + 255) / 256, 256>>>();

    prep_w<<<(4 * HH * HH + 255) / 256, 256>>>(We1, pW1t, 4 * HH, HH);
    prep_w<<<(HH * HH + 255) / 256, 256>>>(We2, pW2t, HH, HH);
    prep_w<<<(3 * HH * HH + 255) / 256, 256>>>(Wv1, pV1t, 3 * HH, HH);
    prep_w<<<(HH * HH + 255) / 256, 256>>>(Wv2, pV2t, HH, HH);

    // edge MLP + scatter
    mlp2_mma<4, true><<<(EE + 127) / 128, TPB, SMEM>>>(
        x, x, ea, u, pW1t, be1, pW2t, be2, out_e, EE);

    eaggr_kernel<<<(NN * HH + 255) / 256, 256>>>();

    // node MLP
    mlp2_mma<3, false><<<(NN + 127) / 128, TPB, SMEM>>>(
        x, nullptr, u, nullptr, pV1t, bv1, pV2t, bv2, out_x, NN);

    graph_reduce_kernel<<<GG, HH>>>(out_x);
    global_mlp_kernel<<<GG, HH>>>(u, Wu1, bu1, Wu2, bu2, out_u);
}

// round 8
// speedup vs baseline: 2.1166x; 1.1700x over previous
#include <cuda_runtime.h>
#include <cstdint>

static constexpr int NN = 50000;
static constexpr int EE = 600000;
static constexpr int GG = 64;
static constexpr int HH = 128;
static constexpr int TPB = 256;   // 8 warps

// ---------------- scratch (no allocations allowed) ----------------
__device__ int   d_row[EE];
__device__ int   d_col[EE];
__device__ int   d_batch[NN];
__device__ int   d_is64;
__device__ float d_e_sum[NN * HH];
__device__ float d_e_aggr[NN * HH];
__device__ float d_cnt[NN];
__device__ float d_e_mean[GG * HH];
__device__ float d_v_mean[GG * HH];
__device__ int   d_start[GG + 1];
__device__ float d_W1t[HH * 4 * HH];   // [N=128][K] transposed, tf32-rounded
__device__ float d_W2t[HH * HH];
__device__ float d_V1t[HH * 3 * HH];
__device__ float d_V2t[HH * HH];

// ---------------- helpers ----------------
__device__ __forceinline__ uint32_t smem_u32(const void* p) {
    uint32_t a;
    asm("{ .reg .u64 t; cvta.to.shared.u64 t, %1; cvt.u32.u64 %0, t; }" : "=r"(a) : "l"(p));
    return a;
}
__device__ __forceinline__ void ldsm4(uint32_t* r, uint32_t addr) {
    asm volatile("ldmatrix.sync.aligned.m8n8.x4.shared.b16 {%0,%1,%2,%3}, [%4];"
        : "=r"(r[0]), "=r"(r[1]), "=r"(r[2]), "=r"(r[3]) : "r"(addr));
}
__device__ __forceinline__ void mma_tf32(float* c, const uint32_t* a, uint32_t b0, uint32_t b1) {
    asm volatile("mma.sync.aligned.m16n8k8.row.col.f32.tf32.tf32.f32 "
        "{%0,%1,%2,%3}, {%4,%5,%6,%7}, {%8,%9}, {%0,%1,%2,%3};"
        : "+f"(c[0]), "+f"(c[1]), "+f"(c[2]), "+f"(c[3])
        : "r"(a[0]), "r"(a[1]), "r"(a[2]), "r"(a[3]), "r"(b0), "r"(b1));
}
__device__ __forceinline__ float tf32r(float v) {
    uint32_t r;
    asm("cvt.rna.tf32.f32 %0, %1;" : "=r"(r) : "f"(v));
    return __uint_as_float(r);
}
__device__ __forceinline__ float4 tf32r4(float4 v) {
    return make_float4(tf32r(v.x), tf32r(v.y), tf32r(v.z), tf32r(v.w));
}
__device__ __forceinline__ void cpa16(uint32_t dst, const void* src) {
    asm volatile("cp.async.cg.shared.global [%0], [%1], 16;" :: "r"(dst), "l"(src));
}
#define CP_COMMIT() asm volatile("cp.async.commit_group;" ::: "memory")
#define CP_WAIT0()  asm volatile("cp.async.wait_group 0;" ::: "memory")
__device__ __forceinline__ float softplusf(float v) {
    float t = __expf(-fabsf(v));
    return fmaxf(v, 0.0f) + __logf(1.0f + t);
}

// ---------------- small prep kernels ----------------
__global__ void detect_kernel(const int* __restrict__ ei) {
    if (threadIdx.x == 0) {
        int all0 = 1;
        for (int i = 0; i < 64; ++i)
            if (ei[2 * i + 1] != 0) { all0 = 0; break; }
        d_is64 = all0;
    }
}
__global__ void convert_kernel(const int* __restrict__ ei, const int* __restrict__ batch) {
    int i = blockIdx.x * 256 + threadIdx.x;
    int is64 = d_is64;
    if (i < EE) {
        d_row[i] = is64 ? ei[2 * i]          : ei[i];
        d_col[i] = is64 ? ei[2 * EE + 2 * i] : ei[EE + i];
    }
    if (i < NN) d_batch[i] = is64 ? batch[2 * i] : batch[i];
}
__global__ void zero_kernel() {
    int i = blockIdx.x * 256 + threadIdx.x;
    if (i < NN * HH) d_e_sum[i] = 0.0f;
    if (i < NN) d_cnt[i] = 0.0f;
}
__global__ void seg_starts_kernel() {
    int v = blockIdx.x * 256 + threadIdx.x;
    if (v >= NN) return;
    int b = d_batch[v];
    int bp = (v == 0) ? -1 : d_batch[v - 1];
    for (int g = bp + 1; g <= b; ++g) d_start[g] = v;
    if (v == NN - 1)
        for (int g = b + 1; g <= GG; ++g) d_start[g] = NN;
}
__global__ void eaggr_kernel() {
    int i = blockIdx.x * 256 + threadIdx.x;
    if (i < NN * HH) {
        float c = d_cnt[i >> 7];
        d_e_aggr[i] = d_e_sum[i] / fmaxf(c, 1.0f);
    }
}
// W [K][N] row-major -> Wt [N][K] tf32-rounded fp32
__global__ void prep_w(const float* __restrict__ W, float* __restrict__ Wt, int K, int N) {
    int i = blockIdx.x * 256 + threadIdx.x;
    if (i < K * N) {
        int k = i / N, n = i % N;
        Wt[n * K + k] = tf32r(W[i]);
    }
}

// ---------------- fused 2-layer MLP via mma.sync tf32, pipelined ----------------
// EDGE: in = [x[row], x[col], edge_attr, u[batch[row]]] (K=512), + scatter
// NODE: in = [x, e_aggr, u[batch]]                      (K=384)
// Dynamic smem (110592 B):
//   [0]      base[128][4]                   (2048)
//   [2048]   sA[2] [128 rows][20 floats]    (2 x 10240)
//   [22528]  sB[2] [128 n   ][20 floats]    (2 x 10240)
//   [43008]  sH1 [128 rows][132 floats]     (67584)
template<int NSEG, bool EDGE>
__global__ void __launch_bounds__(TPB, 2)
mlp2_mma(const float* __restrict__ s0, const float* __restrict__ s1,
         const float* __restrict__ s2, const float* __restrict__ s3,
         const float* __restrict__ W1t, const float* __restrict__ b1,
         const float* __restrict__ W2t, const float* __restrict__ b2,
         float* __restrict__ outp, int M)
{
    extern __shared__ char sm[];
    int* base = (int*)sm;
    char* sA0 = sm + 2048;
    char* sB0 = sm + 22528;
    char* sH1 = sm + 43008;
    const uint32_t aA = smem_u32(sA0), aB = smem_u32(sB0), aH1 = smem_u32(sH1);

    const int tid = threadIdx.x;
    const int w = tid >> 5, l = tid & 31;
    const int m0 = blockIdx.x * 128;

    if (tid < 128) {
        int r = m0 + tid;
        int b0 = 0, b1_ = 0, b2_ = 0, b3_ = 0;
        if (r < M) {
            if (EDGE) {
                int row = d_row[r];
                b0 = row * HH;
                b1_ = d_col[r] * HH;
                b2_ = r * HH;
                b3_ = d_batch[row] * HH;
            } else {
                b0 = r * HH;
                b1_ = r * HH;
                b2_ = d_batch[r] * HH;
            }
        }
        base[tid * 4 + 0] = b0; base[tid * 4 + 1] = b1_;
        base[tid * 4 + 2] = b2_; base[tid * 4 + 3] = b3_;
    }
    __syncthreads();

    const int row = tid >> 1, half = tid & 1;   // staging: 8 floats per thread
    const int K1 = NSEG * 128;
    const int NCH = NSEG * 8;
    const uint32_t stg = (uint32_t)(row * 80 + half * 32);  // staging dst offset

    // ldmatrix lane offsets (byte strides: sA/sB rows 80B, sH1 rows 528B)
    const uint32_t aoffA = (uint32_t)((16 * w + (l & 15)) * 80 + (l >> 4) * 16);
    const uint32_t boff4 = (uint32_t)(((l & 7) + ((l >> 4) & 1) * 8) * 80 + ((l >> 3) & 1) * 16);
    const uint32_t hoffA = (uint32_t)((16 * w + (l & 15)) * 528 + (l >> 4) * 16);

    float acc[16][4];
    #pragma unroll
    for (int j = 0; j < 16; ++j)
        #pragma unroll
        for (int q = 0; q < 4; ++q) acc[j][q] = 0.0f;

    // A-row prefetch helper (gathered), per chunk
    const float* sptr[4];
    sptr[0] = s0;
    sptr[1] = EDGE ? s1 : d_e_aggr;
    sptr[2] = s2;
    sptr[3] = (NSEG == 4) ? s3 : s2;

    // ---------------- layer 1 pipeline prologue ----------------
    float4 f0, f1;
    {   // A(0) prefetch
        const float* ap = sptr[0] + base[row * 4 + 0] + half * 8;
        f0 = *(const float4*)ap;
        f1 = *(const float4*)(ap + 4);
        // B(0) cp.async
        const float* bp = W1t + row * K1 + half * 8;
        cpa16(aB + stg, bp);
        cpa16(aB + stg + 16, bp + 4);
        CP_COMMIT();
    }

    // ---------------- layer 1: chunks of k16, 1 barrier each ----------------
    for (int c = 0; c < NCH; ++c) {
        const uint32_t boffs = (uint32_t)((c & 1) * 10240);
        // stage A(c) (tf32-rounded)
        *(float4*)(sA0 + boffs + stg)      = tf32r4(f0);
        *(float4*)(sA0 + boffs + stg + 16) = tf32r4(f1);
        // prefetch A(c+1)
        {
            int cn = (c + 1 < NCH) ? c + 1 : c;
            int k0n = cn * 16;
            const float* ap = sptr[k0n >> 7] + base[row * 4 + (k0n >> 7)] + (k0n & 127) + half * 8;
            f0 = *(const float4*)ap;
            f1 = *(const float4*)(ap + 4);
        }
        CP_WAIT0();           // B(c) landed
        __syncthreads();      // A(c)/B(c) visible; prior reads of these buffers long done
        // B(c+1) cp.async into the other buffer (post-barrier: safe vs peers' ldsm)
        if (c + 1 < NCH) {
            int k0n = (c + 1) * 16;
            const float* bp = W1t + row * K1 + k0n + half * 8;
            cpa16(aB + (boffs ^ 10240) + stg, bp);
            cpa16(aB + (boffs ^ 10240) + stg + 16, bp + 4);
        }
        CP_COMMIT();

        uint32_t a0[4], a1[4];
        ldsm4(a0, aA + boffs + aoffA);        // k8 #0
        ldsm4(a1, aA + boffs + aoffA + 32);   // k8 #1
        #pragma unroll
        for (int p = 0; p < 8; ++p) {
            uint32_t b[4], b2[4];
            ldsm4(b,  aB + boffs + boff4 + p * 1280);
            ldsm4(b2, aB + boffs + boff4 + p * 1280 + 32);
            mma_tf32(acc[2 * p],     a0, b[0],  b[1]);
            mma_tf32(acc[2 * p + 1], a0, b[2],  b[3]);
            mma_tf32(acc[2 * p],     a1, b2[0], b2[1]);
            mma_tf32(acc[2 * p + 1], a1, b2[2], b2[3]);
        }
    }

    // W2(0) cp.async early (overlaps epilogue-1)
    {
        const float* bp = W2t + row * 128 + half * 8;
        cpa16(aB + stg, bp);
        cpa16(aB + stg + 16, bp + 4);
        CP_COMMIT();
    }

    // ---------------- layer-1 epilogue: bias + softplus -> sH1 ----------------
    {
        const int r0 = 16 * w + (l >> 2);
        #pragma unroll
        for (int j = 0; j < 16; ++j) {
            int col = j * 8 + 2 * (l & 3);
            float bb0 = __ldg(b1 + col), bb1 = __ldg(b1 + col + 1);
            float h00 = tf32r(softplusf(acc[j][0] + bb0));
            float h01 = tf32r(softplusf(acc[j][1] + bb1));
            float h10 = tf32r(softplusf(acc[j][2] + bb0));
            float h11 = tf32r(softplusf(acc[j][3] + bb1));
            *(float2*)(sH1 + r0 * 528 + col * 4)       = make_float2(h00, h01);
            *(float2*)(sH1 + (r0 + 8) * 528 + col * 4) = make_float2(h10, h11);
            acc[j][0] = acc[j][1] = acc[j][2] = acc[j][3] = 0.0f;
        }
    }

    // ---------------- layer 2: K=128, 8 chunks, 1 barrier each ----------------
    for (int c = 0; c < 8; ++c) {
        const uint32_t boffs = (uint32_t)((c & 1) * 10240);
        CP_WAIT0();           // W2(c) landed
        __syncthreads();      // first iter also orders sH1 stores before ldsm
        if (c + 1 < 8) {
            const float* bp = W2t + row * 128 + (c + 1) * 16 + half * 8;
            cpa16(aB + (boffs ^ 10240) + stg, bp);
            cpa16(aB + (boffs ^ 10240) + stg + 16, bp + 4);
        }
        CP_COMMIT();

        const int k0 = c * 16;
        uint32_t a0[4], a1[4];
        ldsm4(a0, aH1 + hoffA + k0 * 4);
        ldsm4(a1, aH1 + hoffA + k0 * 4 + 32);
        #pragma unroll
        for (int p = 0; p < 8; ++p) {
            uint32_t b[4], b2[4];
            ldsm4(b,  aB + boffs + boff4 + p * 1280);
            ldsm4(b2, aB + boffs + boff4 + p * 1280 + 32);
            mma_tf32(acc[2 * p],     a0, b[0],  b[1]);
            mma_tf32(acc[2 * p + 1], a0, b[2],  b[3]);
            mma_tf32(acc[2 * p],     a1, b2[0], b2[1]);
            mma_tf32(acc[2 * p + 1], a1, b2[2], b2[3]);
        }
    }

    // ---------------- epilogue 2: bias + softplus + store (+ scatter) ----------------
    {
        const int r0l = 16 * w + (l >> 2);          // local rows r0l, r0l+8
        const int r0 = m0 + r0l;
        const int db0 = EDGE ? base[r0l * 4 + 0] : 0;
        const int db1 = EDGE ? base[(r0l + 8) * 4 + 0] : 0;
        #pragma unroll
        for (int j = 0; j < 16; ++j) {
            int col = j * 8 + 2 * (l & 3);
            float bb0 = __ldg(b2 + col), bb1 = __ldg(b2 + col + 1);
            float o00 = softplusf(acc[j][0] + bb0);
            float o01 = softplusf(acc[j][1] + bb1);
            float o10 = softplusf(acc[j][2] + bb0);
            float o11 = softplusf(acc[j][3] + bb1);
            if (r0 < M) {
                *(float2*)(outp + (size_t)r0 * HH + col) = make_float2(o00, o01);
                if (EDGE) {
                    atomicAdd(&d_e_sum[db0 + col], o00);
                    atomicAdd(&d_e_sum[db0 + col + 1], o01);
                }
            }
            if (r0 + 8 < M) {
                *(float2*)(outp + (size_t)(r0 + 8) * HH + col) = make_float2(o10, o11);
                if (EDGE) {
                    atomicAdd(&d_e_sum[db1 + col], o10);
                    atomicAdd(&d_e_sum[db1 + col + 1], o11);
                }
            }
        }
        if (EDGE && (l & 3) == 0) {
            if (r0 < M)     atomicAdd(&d_cnt[db0 >> 7], 1.0f);
            if (r0 + 8 < M) atomicAdd(&d_cnt[db1 >> 7], 1.0f);
        }
    }
}

// ---------------- per-graph reductions + global MLP ----------------
__global__ void graph_reduce_kernel(const float* __restrict__ xnew) {
    int g = blockIdx.x;
    int n = threadIdx.x;
    int s = d_start[g], e = d_start[g + 1];
    float se = 0.0f, sv = 0.0f;
    for (int v = s; v < e; ++v) {
        se += d_e_sum[v * HH + n];
        sv += xnew[(size_t)v * HH + n];
    }
    float sc = 0.0f;
    for (int v = s + n; v < e; v += HH) sc += d_cnt[v];
    __shared__ float red[HH];
    red[n] = sc;
    __syncthreads();
    for (int off = 64; off > 0; off >>= 1) {
        if (n < off) red[n] += red[n + off];
        __syncthreads();
    }
    float ec = red[0];
    d_e_mean[g * HH + n] = se / fmaxf(ec, 1.0f);
    d_v_mean[g * HH + n] = sv / fmaxf((float)(e - s), 1.0f);
}

__global__ void global_mlp_kernel(const float* __restrict__ u,
                                  const float* __restrict__ W1, const float* __restrict__ b1,
                                  const float* __restrict__ W2, const float* __restrict__ b2,
                                  float* __restrict__ out_u) {
    __shared__ float in[3 * HH];
    __shared__ float h1s[HH];
    int g = blockIdx.x, n = threadIdx.x;
    in[n]          = u[g * HH + n];
    in[HH + n]     = d_e_mean[g * HH + n];
    in[2 * HH + n] = d_v_mean[g * HH + n];
    __syncthreads();
    float a = b1[n];
    for (int k = 0; k < 3 * HH; ++k) a += in[k] * W1[k * HH + n];
    h1s[n] = softplusf(a);
    __syncthreads();
    float o = b2[n];
    for (int k = 0; k < HH; ++k) o += h1s[k] * W2[k * HH + n];
    out_u[g * HH + n] = softplusf(o);
}

// ---------------- launch ----------------
extern "C" void kernel_launch(void* const* d_in, const int* in_sizes, int n_in,
                              void* d_out, int out_size) {
    const float* x     = (const float*)d_in[0];
    const int*   ei    = (const int*)d_in[1];
    const float* ea    = (const float*)d_in[2];
    const float* u     = (const float*)d_in[3];
    const int*   batch = (const int*)d_in[4];
    const float* We1 = (const float*)d_in[5];
    const float* be1 = (const float*)d_in[6];
    const float* We2 = (const float*)d_in[7];
    const float* be2 = (const float*)d_in[8];
    const float* Wv1 = (const float*)d_in[9];
    const float* bv1 = (const float*)d_in[10];
    const float* Wv2 = (const float*)d_in[11];
    const float* bv2 = (const float*)d_in[12];
    const float* Wu1 = (const float*)d_in[13];
    const float* bu1 = (const float*)d_in[14];
    const float* Wu2 = (const float*)d_in[15];
    const float* bu2 = (const float*)d_in[16];

    float* out   = (float*)d_out;
    float* out_x = out;
    float* out_e = out + (size_t)NN * HH;
    float* out_u = out + (size_t)(NN + EE) * HH;

    float *pW1t, *pW2t, *pV1t, *pV2t;
    cudaGetSymbolAddress((void**)&pW1t, d_W1t);
    cudaGetSymbolAddress((void**)&pW2t, d_W2t);
    cudaGetSymbolAddress((void**)&pV1t, d_V1t);
    cudaGetSymbolAddress((void**)&pV2t, d_V2t);

    const int SMEM = 110592;
    cudaFuncSetAttribute(mlp2_mma<4, true>,  cudaFuncAttributeMaxDynamicSharedMemorySize, SMEM);
    cudaFuncSetAttribute(mlp2_mma<3, false>, cudaFuncAttributeMaxDynamicSharedMemorySize, SMEM);

    detect_kernel<<<1, 32>>>(ei);
    convert_kernel<<<(EE + 255) / 256, 256>>>(ei, batch);
    zero_kernel<<<(NN * HH + 255) / 256, 256>>>();
    seg_starts_kernel<<<(NN + 255) / 256, 256>>>();

    prep_w<<<(4 * HH * HH + 255) / 256, 256>>>(We1, pW1t, 4 * HH, HH);
    prep_w<<<(HH * HH + 255) / 256, 256>>>(We2, pW2t, HH, HH);
    prep_w<<<(3 * HH * HH + 255) / 256, 256>>>(Wv1, pV1t, 3 * HH, HH);
    prep_w<<<(HH * HH + 255) / 256, 256>>>(Wv2, pV2t, HH, HH);

    // edge MLP + scatter
    mlp2_mma<4, true><<<(EE + 127) / 128, TPB, SMEM>>>(
        x, x, ea, u, pW1t, be1, pW2t, be2, out_e, EE);

    eaggr_kernel<<<(NN * HH + 255) / 256, 256>>>();

    // node MLP
    mlp2_mma<3, false><<<(NN + 127) / 128, TPB, SMEM>>>(
        x, nullptr, u, nullptr, pV1t, bv1, pV2t, bv2, out_x, NN);

    graph_reduce_kernel<<<GG, HH>>>(out_x);
    global_mlp_kernel<<<GG, HH>>>(u, Wu1, bu1, Wu2, bu2, out_u);
}